// round 6
// baseline (speedup 1.0000x reference)
#include <cuda_runtime.h>
#include <math.h>

#define HID   256
#define BSZ   64
#define DCS   16
#define NCLS  60
#define NKEY  (NCLS*DCS)     // 960
#define NTOK  (BSZ*DCS)      // 1024
#define QSZ   5
#define TOPK  5
#define TOPKQ 100
#define NQ    400            // 5*5*16 candidates per token
#define CLSBLK (QSZ*DCS)     // 80 rows per class block
#define NPAIR (NTOK*TOPK)    // 5120
#define MAXROWS 7040         // 5120 + 60*31 padded, rounded up
#define MAXTILES 220

// ---------------- scratch (device globals) ----------------
__device__ float g_key_t[NKEY*HID];
__device__ float g_query[NTOK*HID];
__device__ float g_qk   [NTOK*HID];      // folded level-2 query
__device__ float g_W1   [NTOK*NKEY];
__device__ float g_cat  [NTOK*2*HID];    // [qraw | memory_z]
__device__ int   g_cls  [NPAIR];         // class per (token,slot)
__device__ float g_Wc   [HID*HID];
__device__ float g_bc   [HID];
__device__ float g_Wout [HID*2*HID];
__device__ float g_bout [HID];
// class-grouped scoring structures
__device__ int   g_pos  [NPAIR];         // pair -> padded row position
__device__ int   g_rowN [MAXROWS];       // padded row -> token index
__device__ int   g_tiles[MAXTILES*2];    // (class, row0) per tile
__device__ int   g_ntiles;
__device__ float g_S    [MAXROWS*CLSBLK];// scores, class-grouped

// ---------------- 32x64 tile GEMM core, 128 threads ----------------
template<int AMODE, int BMODE>
__device__ __forceinline__ void gemm_tile(
    float* As, float* Bs,
    const float* __restrict__ A, int lda,
    const float* __restrict__ B, int ldb,
    const float* __restrict__ bias,
    float* __restrict__ C, int ldc, int K, int row0, int col0)
{
    const int tid = threadIdx.x;
    const int tx = tid & 15, ty = tid >> 4;
    float acc[4][4] = {};

    for (int k0 = 0; k0 < K; k0 += 16) {
        if (AMODE == 0) {
            const int ar = tid >> 2, ac = (tid & 3) << 2;
            float4 av = *(const float4*)(A + (size_t)(row0 + ar) * lda + k0 + ac);
            As[(ac+0)*36 + ar] = av.x; As[(ac+1)*36 + ar] = av.y;
            As[(ac+2)*36 + ar] = av.z; As[(ac+3)*36 + ar] = av.w;
        } else {
            const int kr = tid >> 3, cm = (tid & 7) << 2;
            float4 av = *(const float4*)(A + (size_t)(k0 + kr) * lda + row0 + cm);
            *(float4*)(As + kr*36 + cm) = av;
        }
        if (BMODE == 1) {
            #pragma unroll
            for (int i = 0; i < 2; i++) {
                const int br = i*32 + (tid >> 2), kc = (tid & 3) << 2;
                float4 bv = *(const float4*)(B + (size_t)(col0 + br) * ldb + k0 + kc);
                Bs[(kc+0)*64 + br] = bv.x; Bs[(kc+1)*64 + br] = bv.y;
                Bs[(kc+2)*64 + br] = bv.z; Bs[(kc+3)*64 + br] = bv.w;
            }
        } else {
            #pragma unroll
            for (int i = 0; i < 2; i++) {
                const int kr = i*8 + (tid >> 4), cn = (tid & 15) << 2;
                *(float4*)(Bs + kr*64 + cn) =
                    *(const float4*)(B + (size_t)(k0 + kr) * ldb + col0 + cn);
            }
        }
        __syncthreads();
        #pragma unroll
        for (int kk = 0; kk < 16; kk++) {
            float4 a = *(const float4*)(As + kk*36 + ty*4);
            float4 b = *(const float4*)(Bs + kk*64 + tx*4);
            acc[0][0] += a.x*b.x; acc[0][1] += a.x*b.y; acc[0][2] += a.x*b.z; acc[0][3] += a.x*b.w;
            acc[1][0] += a.y*b.x; acc[1][1] += a.y*b.y; acc[1][2] += a.y*b.z; acc[1][3] += a.y*b.w;
            acc[2][0] += a.z*b.x; acc[2][1] += a.z*b.y; acc[2][2] += a.z*b.z; acc[2][3] += a.z*b.w;
            acc[3][0] += a.w*b.x; acc[3][1] += a.w*b.y; acc[3][2] += a.w*b.z; acc[3][3] += a.w*b.w;
        }
        __syncthreads();
    }

    float4 bv = make_float4(0.f, 0.f, 0.f, 0.f);
    if (bias) bv = *(const float4*)(bias + col0 + tx*4);
    #pragma unroll
    for (int i = 0; i < 4; i++) {
        float4 o = make_float4(acc[i][0] + bv.x, acc[i][1] + bv.y,
                               acc[i][2] + bv.z, acc[i][3] + bv.w);
        *(float4*)(C + (size_t)(row0 + ty*4 + i) * ldc + col0 + tx*4) = o;
    }
}

// ---------------- launch A ----------------
__global__ void frontA_kernel(const float* __restrict__ memory_key,
                              const float* __restrict__ key_w, const float* __restrict__ key_b,
                              const float* __restrict__ h,
                              const float* __restrict__ query_w, const float* __restrict__ query_b,
                              const float* __restrict__ qq_w, const float* __restrict__ qq_b,
                              const float* __restrict__ kq_w, const float* __restrict__ kq_b,
                              const float* __restrict__ proto_w, const float* __restrict__ proto_b)
{
    __shared__ float As[16*36];
    __shared__ float Bs[16*64];
    const int b = blockIdx.x;
    const int tid = threadIdx.x;

    if (b < 120) {
        gemm_tile<0,1>(As, Bs, memory_key, HID, key_w, HID, key_b,
                       g_key_t, HID, HID, (b >> 2) * 32, (b & 3) * 64);
    } else if (b < 248) {
        const int b2 = b - 120;
        gemm_tile<0,1>(As, Bs, h, HID, query_w, HID, query_b,
                       g_query, HID, HID, (b2 >> 2) * 32, (b2 & 3) * 64);
    } else if (b < 280) {
        const int b2 = b - 248;
        gemm_tile<1,0>(As, Bs, qq_w, HID, kq_w, HID, nullptr,
                       g_Wc, HID, HID, (b2 >> 2) * 32, (b2 & 3) * 64);
    } else if (b < 312) {
        const int b2 = b - 280;
        gemm_tile<0,0>(As, Bs, proto_w, 2*HID, kq_w, HID, nullptr,
                       g_Wout, 2*HID, HID, (b2 >> 2) * 32, (b2 & 3) * 64);
    } else if (b < 328) {
        const int b2 = b - 312;
        #pragma unroll
        for (int t = 0; t < 8; t++) {
            const int idx = t * 128 + tid;
            const int row = b2 * 16 + (idx >> 6);
            const int c4  = idx & 63;
            *(float4*)(g_Wout + (size_t)row * 512 + 256 + c4 * 4) =
                *(const float4*)(proto_w + (size_t)row * 512 + 256 + c4 * 4);
        }
    } else {
        const int j = (b - 328) * 128 + tid;
        float s = 0.f;
        for (int i = 0; i < HID; i++) s += qq_b[i] * kq_w[i * HID + j];
        g_bc[j] = s;
        float s2 = proto_b[j];
        for (int i = 0; i < HID; i++) s2 += kq_b[i] * proto_w[(size_t)j * 512 + i];
        g_bout[j] = s2;
    }
}

// ---------------- launch B ----------------
__global__ void midB_kernel(const float* __restrict__ h)
{
    __shared__ float As[16*36];
    __shared__ float Bs[16*64];
    const int b = blockIdx.x;
    if (b < 128) {
        gemm_tile<0,0>(As, Bs, h, HID, g_Wc, HID, g_bc,
                       g_qk, HID, HID, (b >> 2) * 32, (b & 3) * 64);
    } else {
        const int b2 = b - 128;
        gemm_tile<0,1>(As, Bs, g_query, HID, g_key_t, HID, nullptr,
                       g_W1, NKEY, HID, (b2 / 15) * 32, (b2 % 15) * 64);
    }
}

// ---------------- launch E ----------------
__global__ void outE_kernel(float* __restrict__ out)
{
    __shared__ float As[16*36];
    __shared__ float Bs[16*64];
    const int b = blockIdx.x;
    gemm_tile<0,1>(As, Bs, g_cat, 2*HID, g_Wout, 2*HID, g_bout,
                   out, HID, 2*HID, (b >> 2) * 32, (b & 3) * 64);
}

// ---------------- level 1: top-5 per token ----------------
__global__ void top5_kernel()
{
    const int lane = threadIdx.x & 31;
    const int n = blockIdx.x * 4 + (threadIdx.x >> 5);
    const float* __restrict__ row = g_W1 + (size_t)n * NKEY;

    float v[5]; int ix[5];
    #pragma unroll
    for (int j = 0; j < 5; j++) { v[j] = -INFINITY; ix[j] = 0; }
    for (int k = lane; k < NKEY; k += 32) {
        float x = row[k];
        if (x > v[4]) {
            v[4] = x; ix[4] = k;
            #pragma unroll
            for (int p = 4; p > 0; p--) {
                if (v[p] > v[p-1]) {
                    float tv = v[p]; v[p] = v[p-1]; v[p-1] = tv;
                    int   ti = ix[p]; ix[p] = ix[p-1]; ix[p-1] = ti;
                }
            }
        }
    }

    float selv[5]; int seli[5];
    #pragma unroll
    for (int j = 0; j < 5; j++) {
        float cand = v[0]; int candi = ix[0];
        float bv = cand; int bl = lane;
        #pragma unroll
        for (int off = 16; off; off >>= 1) {
            float ov = __shfl_down_sync(0xffffffffu, bv, off);
            int   ol = __shfl_down_sync(0xffffffffu, bl, off);
            if (ov > bv) { bv = ov; bl = ol; }
        }
        bl = __shfl_sync(0xffffffffu, bl, 0);
        selv[j] = __shfl_sync(0xffffffffu, cand, bl);
        seli[j] = __shfl_sync(0xffffffffu, candi, bl);
        if (lane == bl) {
            #pragma unroll
            for (int p = 0; p < 4; p++) { v[p] = v[p+1]; ix[p] = ix[p+1]; }
            v[4] = -INFINITY;
        }
    }

    const float mx = selv[0];
    float e[5]; float s = 0.f;
    #pragma unroll
    for (int j = 0; j < 5; j++) { e[j] = expf(selv[j] - mx); s += e[j]; }
    const float inv = 1.f / s;

    #pragma unroll
    for (int c = 0; c < 8; c++) {
        const int col = c * 32 + lane;
        float acc = 0.f;
        #pragma unroll
        for (int j = 0; j < 5; j++) acc += e[j] * g_key_t[(size_t)seli[j] * HID + col];
        g_cat[(size_t)n * 512 + 256 + col] = acc * inv;
    }
    #pragma unroll
    for (int j = 0; j < 5; j++)
        if (lane == j) g_cls[n * 5 + j] = seli[j] / DCS;
}

// ---------------- prep: class histogram, padded positions, tile list ----------------
__global__ void prepQ_kernel()
{
    __shared__ int cnt[NCLS], cnt2[NCLS], base[NCLS];
    const int tid = threadIdx.x;
    if (tid < NCLS) { cnt[tid] = 0; cnt2[tid] = 0; }
    for (int i = tid; i < MAXROWS; i += 256) g_rowN[i] = 0;   // pad rows -> token 0
    __syncthreads();
    for (int p = tid; p < NPAIR; p += 256) atomicAdd(&cnt[g_cls[p]], 1);
    __syncthreads();
    if (tid == 0) {
        int run = 0, tt = 0;
        for (int c = 0; c < NCLS; c++) {
            base[c] = run;
            const int nt = (cnt[c] + 31) >> 5;
            for (int t = 0; t < nt; t++) { g_tiles[2*tt] = c; g_tiles[2*tt+1] = t * 32; tt++; }
            run += nt << 5;
        }
        g_ntiles = tt;
    }
    __syncthreads();
    for (int p = tid; p < NPAIR; p += 256) {
        const int c = g_cls[p];
        const int r = atomicAdd(&cnt2[c], 1);
        const int pos = base[c] + r;
        g_pos[p]  = pos;
        g_rowN[pos] = p / TOPK;
    }
}

// ---------------- scoreQ: per-tile GEMM  S[32 x 80] = qk_rows @ classkeys^T ----------------
__global__ void scoreQ_kernel(const float* __restrict__ qkey)
{
    __shared__ float As[32*17];
    __shared__ float Bs[80*17];
    const int b = blockIdx.x;
    if (b >= g_ntiles) return;
    const int c    = g_tiles[2*b];
    const int row0 = g_tiles[2*b+1];
    // padded base of class c = g_pos of any pair? recompute: tiles were emitted in class order,
    // so base = sum of padded counts of lower classes. Store it via rowN trick instead:
    // we kept base only in prep; derive from tile list: first tile of class c has row0==0 and
    // its global row base equals 32*(number of tiles before it). Tiles are contiguous per class.
    // global base for THIS tile = 32*b - row0 + row0 = ... simpler: rows are globally contiguous:
    const int grow0 = b * 32;            // each tile covers exactly 32 padded rows, in order
    const int tid = threadIdx.x;
    const int tx = tid & 15, ty = tid >> 4;
    float acc[2][5] = {};
    const float* __restrict__ Bsrc = qkey + (size_t)c * CLSBLK * HID;
    (void)row0;

    for (int k0 = 0; k0 < HID; k0 += 16) {
        if (tid < 128) {
            const int r = tid >> 2, kc = (tid & 3) << 2;
            const int n = g_rowN[grow0 + r];
            float4 v = *(const float4*)(g_qk + (size_t)n * HID + k0 + kc);
            As[r*17 + kc+0] = v.x; As[r*17 + kc+1] = v.y;
            As[r*17 + kc+2] = v.z; As[r*17 + kc+3] = v.w;
        }
        for (int idx = tid; idx < 320; idx += 256) {
            const int r = idx >> 2, kc = (idx & 3) << 2;
            float4 v = *(const float4*)(Bsrc + (size_t)r * HID + k0 + kc);
            Bs[r*17 + kc+0] = v.x; Bs[r*17 + kc+1] = v.y;
            Bs[r*17 + kc+2] = v.z; Bs[r*17 + kc+3] = v.w;
        }
        __syncthreads();
        #pragma unroll
        for (int kk = 0; kk < 16; kk++) {
            const float a0 = As[ty*17 + kk];
            const float a1 = As[(ty+16)*17 + kk];
            #pragma unroll
            for (int j = 0; j < 5; j++) {
                const float bb = Bs[(tx + 16*j)*17 + kk];
                acc[0][j] += a0 * bb;
                acc[1][j] += a1 * bb;
            }
        }
        __syncthreads();
    }
    #pragma unroll
    for (int i = 0; i < 2; i++)
        #pragma unroll
        for (int j = 0; j < 5; j++)
            g_S[(size_t)(grow0 + ty + 16*i) * CLSBLK + tx + 16*j] = acc[i][j];
}

// ---------------- selgather: radix-select top-100 + softmax + gather ----------------
__device__ __forceinline__ unsigned int f2key(float s) {
    unsigned int b = __float_as_uint(s);
    return (b & 0x80000000u) ? ~b : (b | 0x80000000u);
}

__global__ void selgather_kernel(const float* __restrict__ qkey)
{
    __shared__ float sval[NQ];
    __shared__ unsigned int hist[2048];
    __shared__ int   cls_s[5];
    __shared__ int   pos_s[5];
    __shared__ float sred[8];
    __shared__ unsigned int wtot[16];
    __shared__ float smax_s, sinvZ;
    __shared__ unsigned int sh_prefix;
    __shared__ int sh_K, sh_d, sh_cnt;
    __shared__ float sel_w[160];
    __shared__ int   sel_ri[160];
    __shared__ float4 sacc[256];

    const int n = blockIdx.x;
    const int tid = threadIdx.x;
    const int lane = tid & 31, warp = tid >> 5;

    if (tid < 5) { cls_s[tid] = g_cls[n * 5 + tid]; pos_s[tid] = g_pos[n * 5 + tid]; }
    if (tid == 0) { sh_prefix = 0; sh_K = TOPKQ; }
    __syncthreads();

    // load 400 scores: 5 contiguous 80-float chunks
    for (int idx = tid; idx < NQ; idx += 256) {
        const int k = idx / CLSBLK, r = idx - k * CLSBLK;
        sval[idx] = g_S[(size_t)pos_s[k] * CLSBLK + r];
    }
    __syncthreads();

    const bool has2 = (tid < NQ - 256);
    const float s1 = sval[tid];
    const float s2 = has2 ? sval[tid + 256] : 0.f;
    const unsigned int u1 = f2key(s1);
    const unsigned int u2 = has2 ? f2key(s2) : 0u;

    // block max
    float mloc = has2 ? fmaxf(s1, s2) : s1;
    #pragma unroll
    for (int off = 16; off; off >>= 1) mloc = fmaxf(mloc, __shfl_down_sync(0xffffffffu, mloc, off));
    if (lane == 0) sred[warp] = mloc;
    __syncthreads();
    if (tid == 0) {
        float mm = sred[0];
        #pragma unroll
        for (int i = 1; i < 8; i++) mm = fmaxf(mm, sred[i]);
        smax_s = mm;
    }
    __syncthreads();

    // radix select: exact 100th-largest key
    #pragma unroll
    for (int pass = 0; pass < 3; pass++) {
        const int shift = (pass == 0) ? 21 : (pass == 1) ? 10 : 0;
        const unsigned int binmask = (pass == 2) ? 1023u : 2047u;
        const unsigned int himask = (pass == 0) ? 0u : (pass == 1) ? 0xFFE00000u : 0xFFFFFC00u;
        const int bpt = (pass == 2) ? 4 : 8;

        #pragma unroll
        for (int i = 0; i < 8; i++) hist[tid * 8 + i] = 0;
        __syncthreads();

        const unsigned int pref = sh_prefix;
        if ((u1 & himask) == (pref & himask)) atomicAdd(&hist[(u1 >> shift) & binmask], 1u);
        if (has2 && (u2 & himask) == (pref & himask)) atomicAdd(&hist[(u2 >> shift) & binmask], 1u);
        __syncthreads();

        unsigned int lsum = 0;
        #pragma unroll
        for (int i = 0; i < 8; i++) if (i < bpt) lsum += hist[tid * bpt + i];
        unsigned int sincl = lsum;
        #pragma unroll
        for (int off = 1; off < 32; off <<= 1) {
            unsigned int y = __shfl_down_sync(0xffffffffu, sincl, off);
            if (lane + off < 32) sincl += y;
        }
        if (lane == 0) wtot[warp] = sincl;
        __syncthreads();
        unsigned int suf_hi = 0;
        for (int w2 = warp + 1; w2 < 8; w2++) suf_hi += wtot[w2];
        const unsigned int sexcl = suf_hi + (sincl - lsum);
        const unsigned int K = (unsigned int)sh_K;
        if (lsum > 0 && sexcl < K && sexcl + lsum >= K) {
            unsigned int run = sexcl;
            for (int i = bpt - 1; i >= 0; i--) {
                const unsigned int c = hist[tid * bpt + i];
                if (run < K && run + c >= K) {
                    sh_prefix = pref | ((unsigned int)(tid * bpt + i) << shift);
                    sh_K = (int)(K - run);
                    sh_d = (int)c;
                    break;
                }
                run += c;
            }
        }
        __syncthreads();
    }

    const unsigned int tkey = sh_prefix;
    const float scale_t = (float)sh_K / (float)sh_d;

    float w1 = 0.f, w2 = 0.f;
    if (u1 > tkey)       w1 = expf(s1 - smax_s);
    else if (u1 == tkey) w1 = expf(s1 - smax_s) * scale_t;
    if (has2) {
        if (u2 > tkey)       w2 = expf(s2 - smax_s);
        else if (u2 == tkey) w2 = expf(s2 - smax_s) * scale_t;
    }
    float z = w1 + w2;
    #pragma unroll
    for (int off = 16; off; off >>= 1) z += __shfl_down_sync(0xffffffffu, z, off);
    if (lane == 0) sred[warp] = z;
    __syncthreads();
    if (tid == 0) {
        float t = 0.f;
        #pragma unroll
        for (int i = 0; i < 8; i++) t += sred[i];
        sinvZ = 1.f / t;
    }
    __syncthreads();
    const float invZ = sinvZ;

    // deterministic compaction
    const bool p1 = (w1 > 0.f);
    unsigned int bal = __ballot_sync(0xffffffffu, p1);
    int lp1 = __popc(bal & ((1u << lane) - 1u));
    if (lane == 0) wtot[warp] = __popc(bal);
    const bool p2 = has2 && (w2 > 0.f);
    unsigned int bal2 = __ballot_sync(0xffffffffu, p2);
    int lp2 = __popc(bal2 & ((1u << lane) - 1u));
    if (lane == 0) wtot[8 + warp] = __popc(bal2);
    __syncthreads();
    int baseA = 0, totA = 0;
    #pragma unroll
    for (int i = 0; i < 8; i++) { if (i < warp) baseA += wtot[i]; totA += wtot[i]; }
    int baseB = totA;
    for (int i = 0; i < warp; i++) baseB += wtot[8 + i];
    if (p1) {
        const int pos = baseA + lp1;
        if (pos < 160) {
            const int m = tid;
            sel_w[pos]  = w1 * invZ;
            sel_ri[pos] = cls_s[m / CLSBLK] * CLSBLK + (m % CLSBLK);
        }
    }
    if (p2) {
        const int pos = baseB + lp2;
        if (pos < 160) {
            const int m = tid + 256;
            sel_w[pos]  = w2 * invZ;
            sel_ri[pos] = cls_s[m / CLSBLK] * CLSBLK + (m % CLSBLK);
        }
    }
    if (tid == 0) {
        int tb = totA;
        #pragma unroll
        for (int i = 0; i < 8; i++) tb += wtot[8 + i];
        sh_cnt = (tb < 160) ? tb : 160;
    }
    __syncthreads();
    const int cnt = sh_cnt;

    // weighted sum of raw rows
    const int rg = tid >> 6, c4 = tid & 63;
    const float4* __restrict__ q4 = (const float4*)qkey;
    float4 acc = make_float4(0.f, 0.f, 0.f, 0.f);
    for (int j = rg; j < cnt; j += 4) {
        const float w = sel_w[j];
        const float4 v = q4[(size_t)sel_ri[j] * 64 + c4];
        acc.x += w * v.x; acc.y += w * v.y; acc.z += w * v.z; acc.w += w * v.w;
    }
    sacc[rg * 64 + c4] = acc;
    __syncthreads();
    if (rg == 0) {
        const float4 p0v = sacc[c4], p1v = sacc[64 + c4], p2v = sacc[128 + c4], p3v = sacc[192 + c4];
        float4 o = make_float4(p0v.x + p1v.x + p2v.x + p3v.x, p0v.y + p1v.y + p2v.y + p3v.y,
                               p0v.z + p1v.z + p2v.z + p3v.z, p0v.w + p1v.w + p2v.w + p3v.w);
        *(float4*)(g_cat + (size_t)n * 512 + c4 * 4) = o;
    }
}

// ---------------- host ----------------
extern "C" void kernel_launch(void* const* d_in, const int* in_sizes, int n_in,
                              void* d_out, int out_size)
{
    const float* h          = (const float*)d_in[0];
    const float* memory_key = (const float*)d_in[3];
    const float* queue_key  = (const float*)d_in[4];
    const float* key_w      = (const float*)d_in[5];
    const float* key_b      = (const float*)d_in[6];
    const float* query_w    = (const float*)d_in[7];
    const float* query_b    = (const float*)d_in[8];
    const float* kq_w       = (const float*)d_in[9];
    const float* kq_b       = (const float*)d_in[10];
    const float* qq_w       = (const float*)d_in[11];
    const float* qq_b       = (const float*)d_in[12];
    const float* proto_w    = (const float*)d_in[13];
    const float* proto_b    = (const float*)d_in[14];
    float* out = (float*)d_out;

    frontA_kernel<<<330, 128>>>(memory_key, key_w, key_b, h, query_w, query_b,
                                qq_w, qq_b, kq_w, kq_b, proto_w, proto_b);
    midB_kernel<<<608, 128>>>(h);
    top5_kernel<<<NTOK/4, 128>>>();
    prepQ_kernel<<<1, 256>>>();
    scoreQ_kernel<<<MAXTILES, 256>>>(queue_key);
    selgather_kernel<<<NTOK, 256>>>(queue_key);
    outE_kernel<<<128, 128>>>(out);
}

// round 7
// speedup vs baseline: 1.0410x; 1.0410x over previous
#include <cuda_runtime.h>
#include <math.h>

#define HID   256
#define BSZ   64
#define DCS   16
#define NCLS  60
#define NKEY  (NCLS*DCS)     // 960
#define NTOK  (BSZ*DCS)      // 1024
#define QSZ   5
#define TOPK  5
#define TOPKQ 100
#define NQ    400            // 5*5*16 candidates per token
#define CLSBLK (QSZ*DCS)     // 80 rows per class block
#define NPAIR (NTOK*TOPK)    // 5120
#define MAXROWS 7040         // 5120 + 60*31 padded, rounded up
#define MAXTILES 220

// ---------------- scratch (device globals) ----------------
__device__ float g_key_t[NKEY*HID];
__device__ float g_query[NTOK*HID];
__device__ float g_qk   [NTOK*HID];      // folded level-2 query
__device__ float g_W1   [NTOK*NKEY];
__device__ float g_cat  [NTOK*2*HID];    // [qraw | memory_z]
__device__ int   g_cls  [NPAIR];         // class per (token,slot)
__device__ float g_Wc   [HID*HID];
__device__ float g_bc   [HID];
__device__ float g_Wout [HID*2*HID];
__device__ float g_bout [HID];
// class-grouped scoring structures
__device__ int   g_pos  [NPAIR];         // pair -> padded row position
__device__ int   g_rowN [MAXROWS];       // padded row -> token index
__device__ int   g_tiles[MAXTILES*2];    // (class, row0) per tile
__device__ int   g_ntiles;
__device__ float g_S    [MAXROWS*CLSBLK];// scores, class-grouped

// ---------------- 32x64 tile GEMM core, 128 threads ----------------
template<int AMODE, int BMODE>
__device__ __forceinline__ void gemm_tile(
    float* As, float* Bs,
    const float* __restrict__ A, int lda,
    const float* __restrict__ B, int ldb,
    const float* __restrict__ bias,
    float* __restrict__ C, int ldc, int K, int row0, int col0)
{
    const int tid = threadIdx.x;
    const int tx = tid & 15, ty = tid >> 4;
    float acc[4][4] = {};

    for (int k0 = 0; k0 < K; k0 += 16) {
        if (AMODE == 0) {
            const int ar = tid >> 2, ac = (tid & 3) << 2;
            float4 av = *(const float4*)(A + (size_t)(row0 + ar) * lda + k0 + ac);
            As[(ac+0)*36 + ar] = av.x; As[(ac+1)*36 + ar] = av.y;
            As[(ac+2)*36 + ar] = av.z; As[(ac+3)*36 + ar] = av.w;
        } else {
            const int kr = tid >> 3, cm = (tid & 7) << 2;
            float4 av = *(const float4*)(A + (size_t)(k0 + kr) * lda + row0 + cm);
            *(float4*)(As + kr*36 + cm) = av;
        }
        if (BMODE == 1) {
            #pragma unroll
            for (int i = 0; i < 2; i++) {
                const int br = i*32 + (tid >> 2), kc = (tid & 3) << 2;
                float4 bv = *(const float4*)(B + (size_t)(col0 + br) * ldb + k0 + kc);
                Bs[(kc+0)*64 + br] = bv.x; Bs[(kc+1)*64 + br] = bv.y;
                Bs[(kc+2)*64 + br] = bv.z; Bs[(kc+3)*64 + br] = bv.w;
            }
        } else {
            #pragma unroll
            for (int i = 0; i < 2; i++) {
                const int kr = i*8 + (tid >> 4), cn = (tid & 15) << 2;
                *(float4*)(Bs + kr*64 + cn) =
                    *(const float4*)(B + (size_t)(k0 + kr) * ldb + col0 + cn);
            }
        }
        __syncthreads();
        #pragma unroll
        for (int kk = 0; kk < 16; kk++) {
            float4 a = *(const float4*)(As + kk*36 + ty*4);
            float4 b = *(const float4*)(Bs + kk*64 + tx*4);
            acc[0][0] += a.x*b.x; acc[0][1] += a.x*b.y; acc[0][2] += a.x*b.z; acc[0][3] += a.x*b.w;
            acc[1][0] += a.y*b.x; acc[1][1] += a.y*b.y; acc[1][2] += a.y*b.z; acc[1][3] += a.y*b.w;
            acc[2][0] += a.z*b.x; acc[2][1] += a.z*b.y; acc[2][2] += a.z*b.z; acc[2][3] += a.z*b.w;
            acc[3][0] += a.w*b.x; acc[3][1] += a.w*b.y; acc[3][2] += a.w*b.z; acc[3][3] += a.w*b.w;
        }
        __syncthreads();
    }

    float4 bv = make_float4(0.f, 0.f, 0.f, 0.f);
    if (bias) bv = *(const float4*)(bias + col0 + tx*4);
    #pragma unroll
    for (int i = 0; i < 4; i++) {
        float4 o = make_float4(acc[i][0] + bv.x, acc[i][1] + bv.y,
                               acc[i][2] + bv.z, acc[i][3] + bv.w);
        *(float4*)(C + (size_t)(row0 + ty*4 + i) * ldc + col0 + tx*4) = o;
    }
}

// ---------------- launch A ----------------
__global__ void frontA_kernel(const float* __restrict__ memory_key,
                              const float* __restrict__ key_w, const float* __restrict__ key_b,
                              const float* __restrict__ h,
                              const float* __restrict__ query_w, const float* __restrict__ query_b,
                              const float* __restrict__ qq_w, const float* __restrict__ qq_b,
                              const float* __restrict__ kq_w, const float* __restrict__ kq_b,
                              const float* __restrict__ proto_w, const float* __restrict__ proto_b)
{
    __shared__ float As[16*36];
    __shared__ float Bs[16*64];
    const int b = blockIdx.x;
    const int tid = threadIdx.x;

    if (b < 120) {
        gemm_tile<0,1>(As, Bs, memory_key, HID, key_w, HID, key_b,
                       g_key_t, HID, HID, (b >> 2) * 32, (b & 3) * 64);
    } else if (b < 248) {
        const int b2 = b - 120;
        gemm_tile<0,1>(As, Bs, h, HID, query_w, HID, query_b,
                       g_query, HID, HID, (b2 >> 2) * 32, (b2 & 3) * 64);
    } else if (b < 280) {
        const int b2 = b - 248;
        gemm_tile<1,0>(As, Bs, qq_w, HID, kq_w, HID, nullptr,
                       g_Wc, HID, HID, (b2 >> 2) * 32, (b2 & 3) * 64);
    } else if (b < 312) {
        const int b2 = b - 280;
        gemm_tile<0,0>(As, Bs, proto_w, 2*HID, kq_w, HID, nullptr,
                       g_Wout, 2*HID, HID, (b2 >> 2) * 32, (b2 & 3) * 64);
    } else if (b < 328) {
        const int b2 = b - 312;
        #pragma unroll
        for (int t = 0; t < 8; t++) {
            const int idx = t * 128 + tid;
            const int row = b2 * 16 + (idx >> 6);
            const int c4  = idx & 63;
            *(float4*)(g_Wout + (size_t)row * 512 + 256 + c4 * 4) =
                *(const float4*)(proto_w + (size_t)row * 512 + 256 + c4 * 4);
        }
    } else {
        const int j = (b - 328) * 128 + tid;
        float s = 0.f;
        for (int i = 0; i < HID; i++) s += qq_b[i] * kq_w[i * HID + j];
        g_bc[j] = s;
        float s2 = proto_b[j];
        for (int i = 0; i < HID; i++) s2 += kq_b[i] * proto_w[(size_t)j * 512 + i];
        g_bout[j] = s2;
    }
}

// ---------------- launch B ----------------
__global__ void midB_kernel(const float* __restrict__ h)
{
    __shared__ float As[16*36];
    __shared__ float Bs[16*64];
    const int b = blockIdx.x;
    if (b < 128) {
        gemm_tile<0,0>(As, Bs, h, HID, g_Wc, HID, g_bc,
                       g_qk, HID, HID, (b >> 2) * 32, (b & 3) * 64);
    } else {
        const int b2 = b - 128;
        gemm_tile<0,1>(As, Bs, g_query, HID, g_key_t, HID, nullptr,
                       g_W1, NKEY, HID, (b2 / 15) * 32, (b2 % 15) * 64);
    }
}

// ---------------- launch E ----------------
__global__ void outE_kernel(float* __restrict__ out)
{
    __shared__ float As[16*36];
    __shared__ float Bs[16*64];
    const int b = blockIdx.x;
    gemm_tile<0,1>(As, Bs, g_cat, 2*HID, g_Wout, 2*HID, g_bout,
                   out, HID, 2*HID, (b >> 2) * 32, (b & 3) * 64);
}

// ---------------- level 1: top-5 per token ----------------
__global__ void top5_kernel()
{
    const int lane = threadIdx.x & 31;
    const int n = blockIdx.x * 4 + (threadIdx.x >> 5);
    const float* __restrict__ row = g_W1 + (size_t)n * NKEY;

    float v[5]; int ix[5];
    #pragma unroll
    for (int j = 0; j < 5; j++) { v[j] = -INFINITY; ix[j] = 0; }
    for (int k = lane; k < NKEY; k += 32) {
        float x = row[k];
        if (x > v[4]) {
            v[4] = x; ix[4] = k;
            #pragma unroll
            for (int p = 4; p > 0; p--) {
                if (v[p] > v[p-1]) {
                    float tv = v[p]; v[p] = v[p-1]; v[p-1] = tv;
                    int   ti = ix[p]; ix[p] = ix[p-1]; ix[p-1] = ti;
                }
            }
        }
    }

    float selv[5]; int seli[5];
    #pragma unroll
    for (int j = 0; j < 5; j++) {
        float cand = v[0]; int candi = ix[0];
        float bv = cand; int bl = lane;
        #pragma unroll
        for (int off = 16; off; off >>= 1) {
            float ov = __shfl_down_sync(0xffffffffu, bv, off);
            int   ol = __shfl_down_sync(0xffffffffu, bl, off);
            if (ov > bv) { bv = ov; bl = ol; }
        }
        bl = __shfl_sync(0xffffffffu, bl, 0);
        selv[j] = __shfl_sync(0xffffffffu, cand, bl);
        seli[j] = __shfl_sync(0xffffffffu, candi, bl);
        if (lane == bl) {
            #pragma unroll
            for (int p = 0; p < 4; p++) { v[p] = v[p+1]; ix[p] = ix[p+1]; }
            v[4] = -INFINITY;
        }
    }

    const float mx = selv[0];
    float e[5]; float s = 0.f;
    #pragma unroll
    for (int j = 0; j < 5; j++) { e[j] = expf(selv[j] - mx); s += e[j]; }
    const float inv = 1.f / s;

    #pragma unroll
    for (int c = 0; c < 8; c++) {
        const int col = c * 32 + lane;
        float acc = 0.f;
        #pragma unroll
        for (int j = 0; j < 5; j++) acc += e[j] * g_key_t[(size_t)seli[j] * HID + col];
        g_cat[(size_t)n * 512 + 256 + col] = acc * inv;
    }
    #pragma unroll
    for (int j = 0; j < 5; j++)
        if (lane == j) g_cls[n * 5 + j] = seli[j] / DCS;
}

// ---------------- prep: class histogram, padded positions, tile list (parallel) ----------------
__global__ void prepQ_kernel()
{
    __shared__ int cnt[NCLS], cnt2[NCLS], base[NCLS], tbase[NCLS];
    const int tid = threadIdx.x;
    if (tid < NCLS) { cnt[tid] = 0; cnt2[tid] = 0; }
    for (int i = tid; i < MAXROWS; i += 256) g_rowN[i] = 0;   // pad rows -> token 0
    __syncthreads();
    for (int p = tid; p < NPAIR; p += 256) atomicAdd(&cnt[g_cls[p]], 1);
    __syncthreads();
    if (tid == 0) {                                  // 60-iter register scan only
        int run = 0, tt = 0;
        for (int c = 0; c < NCLS; c++) {
            base[c] = run;
            tbase[c] = tt;
            const int nt = (cnt[c] + 31) >> 5;
            tt  += nt;
            run += nt << 5;
        }
        g_ntiles = tt;
    }
    __syncthreads();
    if (tid < NCLS) {                                // parallel tile emission (thread per class)
        const int nt = (cnt[tid] + 31) >> 5;
        const int t0 = tbase[tid];
        for (int t = 0; t < nt; t++) {
            g_tiles[2*(t0+t)]   = tid;
            g_tiles[2*(t0+t)+1] = t * 32;
        }
    }
    for (int p = tid; p < NPAIR; p += 256) {         // position assignment
        const int c = g_cls[p];
        const int r = atomicAdd(&cnt2[c], 1);
        const int pos = base[c] + r;
        g_pos[p]  = pos;
        g_rowN[pos] = p / TOPK;
    }
}

// ---------------- scoreQ: per-tile GEMM  S[32 x 80] = qk_rows @ classkeys^T ----------------
__global__ void scoreQ_kernel(const float* __restrict__ qkey)
{
    __shared__ float As[32*17];
    __shared__ float Bs[80*17];
    const int b = blockIdx.x;
    if (b >= g_ntiles) return;
    const int c = g_tiles[2*b];
    const int grow0 = b * 32;            // tiles cover contiguous padded rows in order
    const int tid = threadIdx.x;
    const int tx = tid & 15, ty = tid >> 4;
    float acc[2][5] = {};
    const float* __restrict__ Bsrc = qkey + (size_t)c * CLSBLK * HID;

    for (int k0 = 0; k0 < HID; k0 += 16) {
        if (tid < 128) {
            const int r = tid >> 2, kc = (tid & 3) << 2;
            const int n = g_rowN[grow0 + r];
            float4 v = *(const float4*)(g_qk + (size_t)n * HID + k0 + kc);
            As[r*17 + kc+0] = v.x; As[r*17 + kc+1] = v.y;
            As[r*17 + kc+2] = v.z; As[r*17 + kc+3] = v.w;
        }
        for (int idx = tid; idx < 320; idx += 256) {
            const int r = idx >> 2, kc = (idx & 3) << 2;
            float4 v = *(const float4*)(Bsrc + (size_t)r * HID + k0 + kc);
            Bs[r*17 + kc+0] = v.x; Bs[r*17 + kc+1] = v.y;
            Bs[r*17 + kc+2] = v.z; Bs[r*17 + kc+3] = v.w;
        }
        __syncthreads();
        #pragma unroll
        for (int kk = 0; kk < 16; kk++) {
            const float a0 = As[ty*17 + kk];
            const float a1 = As[(ty+16)*17 + kk];
            #pragma unroll
            for (int j = 0; j < 5; j++) {
                const float bb = Bs[(tx + 16*j)*17 + kk];
                acc[0][j] += a0 * bb;
                acc[1][j] += a1 * bb;
            }
        }
        __syncthreads();
    }
    #pragma unroll
    for (int i = 0; i < 2; i++)
        #pragma unroll
        for (int j = 0; j < 5; j++)
            g_S[(size_t)(grow0 + ty + 16*i) * CLSBLK + tx + 16*j] = acc[i][j];
}

// ---------------- selgather: radix-select top-100 + softmax + gather ----------------
__device__ __forceinline__ unsigned int f2key(float s) {
    unsigned int b = __float_as_uint(s);
    return (b & 0x80000000u) ? ~b : (b | 0x80000000u);
}

__global__ void selgather_kernel(const float* __restrict__ qkey)
{
    __shared__ float sval[NQ];
    __shared__ unsigned int hist[2048];
    __shared__ int   cls_s[5];
    __shared__ int   pos_s[5];
    __shared__ float sred[8];
    __shared__ unsigned int wtot[16];
    __shared__ float smax_s, sinvZ;
    __shared__ unsigned int sh_prefix;
    __shared__ int sh_K, sh_d, sh_cnt;
    __shared__ float sel_w[160];
    __shared__ int   sel_ri[160];
    __shared__ float4 sacc[256];

    const int n = blockIdx.x;
    const int tid = threadIdx.x;
    const int lane = tid & 31, warp = tid >> 5;

    if (tid < 5) { cls_s[tid] = g_cls[n * 5 + tid]; pos_s[tid] = g_pos[n * 5 + tid]; }
    if (tid == 0) { sh_prefix = 0; sh_K = TOPKQ; }
    __syncthreads();

    // load 400 scores: 5 contiguous 80-float chunks
    for (int idx = tid; idx < NQ; idx += 256) {
        const int k = idx / CLSBLK, r = idx - k * CLSBLK;
        sval[idx] = g_S[(size_t)pos_s[k] * CLSBLK + r];
    }
    __syncthreads();

    const bool has2 = (tid < NQ - 256);
    const float s1 = sval[tid];
    const float s2 = has2 ? sval[tid + 256] : 0.f;
    const unsigned int u1 = f2key(s1);
    const unsigned int u2 = has2 ? f2key(s2) : 0u;

    // block max
    float mloc = has2 ? fmaxf(s1, s2) : s1;
    #pragma unroll
    for (int off = 16; off; off >>= 1) mloc = fmaxf(mloc, __shfl_down_sync(0xffffffffu, mloc, off));
    if (lane == 0) sred[warp] = mloc;
    __syncthreads();
    if (tid == 0) {
        float mm = sred[0];
        #pragma unroll
        for (int i = 1; i < 8; i++) mm = fmaxf(mm, sred[i]);
        smax_s = mm;
    }
    __syncthreads();

    // radix select: exact 100th-largest key
    #pragma unroll
    for (int pass = 0; pass < 3; pass++) {
        const int shift = (pass == 0) ? 21 : (pass == 1) ? 10 : 0;
        const unsigned int binmask = (pass == 2) ? 1023u : 2047u;
        const unsigned int himask = (pass == 0) ? 0u : (pass == 1) ? 0xFFE00000u : 0xFFFFFC00u;
        const int bpt = (pass == 2) ? 4 : 8;

        #pragma unroll
        for (int i = 0; i < 8; i++) hist[tid * 8 + i] = 0;
        __syncthreads();

        const unsigned int pref = sh_prefix;
        if ((u1 & himask) == (pref & himask)) atomicAdd(&hist[(u1 >> shift) & binmask], 1u);
        if (has2 && (u2 & himask) == (pref & himask)) atomicAdd(&hist[(u2 >> shift) & binmask], 1u);
        __syncthreads();

        unsigned int lsum = 0;
        #pragma unroll
        for (int i = 0; i < 8; i++) if (i < bpt) lsum += hist[tid * bpt + i];
        unsigned int sincl = lsum;
        #pragma unroll
        for (int off = 1; off < 32; off <<= 1) {
            unsigned int y = __shfl_down_sync(0xffffffffu, sincl, off);
            if (lane + off < 32) sincl += y;
        }
        if (lane == 0) wtot[warp] = sincl;
        __syncthreads();
        unsigned int suf_hi = 0;
        for (int w2 = warp + 1; w2 < 8; w2++) suf_hi += wtot[w2];
        const unsigned int sexcl = suf_hi + (sincl - lsum);
        const unsigned int K = (unsigned int)sh_K;
        if (lsum > 0 && sexcl < K && sexcl + lsum >= K) {
            unsigned int run = sexcl;
            for (int i = bpt - 1; i >= 0; i--) {
                const unsigned int c = hist[tid * bpt + i];
                if (run < K && run + c >= K) {
                    sh_prefix = pref | ((unsigned int)(tid * bpt + i) << shift);
                    sh_K = (int)(K - run);
                    sh_d = (int)c;
                    break;
                }
                run += c;
            }
        }
        __syncthreads();
    }

    const unsigned int tkey = sh_prefix;
    const float scale_t = (float)sh_K / (float)sh_d;

    float w1 = 0.f, w2 = 0.f;
    if (u1 > tkey)       w1 = expf(s1 - smax_s);
    else if (u1 == tkey) w1 = expf(s1 - smax_s) * scale_t;
    if (has2) {
        if (u2 > tkey)       w2 = expf(s2 - smax_s);
        else if (u2 == tkey) w2 = expf(s2 - smax_s) * scale_t;
    }
    float z = w1 + w2;
    #pragma unroll
    for (int off = 16; off; off >>= 1) z += __shfl_down_sync(0xffffffffu, z, off);
    if (lane == 0) sred[warp] = z;
    __syncthreads();
    if (tid == 0) {
        float t = 0.f;
        #pragma unroll
        for (int i = 0; i < 8; i++) t += sred[i];
        sinvZ = 1.f / t;
    }
    __syncthreads();
    const float invZ = sinvZ;

    // deterministic compaction
    const bool p1 = (w1 > 0.f);
    unsigned int bal = __ballot_sync(0xffffffffu, p1);
    int lp1 = __popc(bal & ((1u << lane) - 1u));
    if (lane == 0) wtot[warp] = __popc(bal);
    const bool p2 = has2 && (w2 > 0.f);
    unsigned int bal2 = __ballot_sync(0xffffffffu, p2);
    int lp2 = __popc(bal2 & ((1u << lane) - 1u));
    if (lane == 0) wtot[8 + warp] = __popc(bal2);
    __syncthreads();
    int baseA = 0, totA = 0;
    #pragma unroll
    for (int i = 0; i < 8; i++) { if (i < warp) baseA += wtot[i]; totA += wtot[i]; }
    int baseB = totA;
    for (int i = 0; i < warp; i++) baseB += wtot[8 + i];
    if (p1) {
        const int pos = baseA + lp1;
        if (pos < 160) {
            const int m = tid;
            sel_w[pos]  = w1 * invZ;
            sel_ri[pos] = cls_s[m / CLSBLK] * CLSBLK + (m % CLSBLK);
        }
    }
    if (p2) {
        const int pos = baseB + lp2;
        if (pos < 160) {
            const int m = tid + 256;
            sel_w[pos]  = w2 * invZ;
            sel_ri[pos] = cls_s[m / CLSBLK] * CLSBLK + (m % CLSBLK);
        }
    }
    if (tid == 0) {
        int tb = totA;
        #pragma unroll
        for (int i = 0; i < 8; i++) tb += wtot[8 + i];
        sh_cnt = (tb < 160) ? tb : 160;
    }
    __syncthreads();
    const int cnt = sh_cnt;

    // weighted sum of raw rows
    const int rg = tid >> 6, c4 = tid & 63;
    const float4* __restrict__ q4 = (const float4*)qkey;
    float4 acc = make_float4(0.f, 0.f, 0.f, 0.f);
    for (int j = rg; j < cnt; j += 4) {
        const float w = sel_w[j];
        const float4 v = q4[(size_t)sel_ri[j] * 64 + c4];
        acc.x += w * v.x; acc.y += w * v.y; acc.z += w * v.z; acc.w += w * v.w;
    }
    sacc[rg * 64 + c4] = acc;
    __syncthreads();
    if (rg == 0) {
        const float4 p0v = sacc[c4], p1v = sacc[64 + c4], p2v = sacc[128 + c4], p3v = sacc[192 + c4];
        float4 o = make_float4(p0v.x + p1v.x + p2v.x + p3v.x, p0v.y + p1v.y + p2v.y + p3v.y,
                               p0v.z + p1v.z + p2v.z + p3v.z, p0v.w + p1v.w + p2v.w + p3v.w);
        *(float4*)(g_cat + (size_t)n * 512 + c4 * 4) = o;
    }
}

// ---------------- host ----------------
extern "C" void kernel_launch(void* const* d_in, const int* in_sizes, int n_in,
                              void* d_out, int out_size)
{
    const float* h          = (const float*)d_in[0];
    const float* memory_key = (const float*)d_in[3];
    const float* queue_key  = (const float*)d_in[4];
    const float* key_w      = (const float*)d_in[5];
    const float* key_b      = (const float*)d_in[6];
    const float* query_w    = (const float*)d_in[7];
    const float* query_b    = (const float*)d_in[8];
    const float* kq_w       = (const float*)d_in[9];
    const float* kq_b       = (const float*)d_in[10];
    const float* qq_w       = (const float*)d_in[11];
    const float* qq_b       = (const float*)d_in[12];
    const float* proto_w    = (const float*)d_in[13];
    const float* proto_b    = (const float*)d_in[14];
    float* out = (float*)d_out;

    frontA_kernel<<<330, 128>>>(memory_key, key_w, key_b, h, query_w, query_b,
                                qq_w, qq_b, kq_w, kq_b, proto_w, proto_b);
    midB_kernel<<<608, 128>>>(h);
    top5_kernel<<<NTOK/4, 128>>>();
    prepQ_kernel<<<1, 256>>>();
    scoreQ_kernel<<<MAXTILES, 256>>>(queue_key);
    selgather_kernel<<<NTOK, 256>>>(queue_key);
    outE_kernel<<<128, 128>>>(out);
}